// round 2
// baseline (speedup 1.0000x reference)
#include <cuda_runtime.h>
#include <cuda_bf16.h>
#include <math.h>

// Problem constants
#define BB 2
#define TT 2048
#define DD 2048
#define HH 16
#define KVH 4
#define HD 128
#define REP (HH / KVH)
#define NTOK (BB * TT)   // 4096

// Scratch (device globals — no allocation allowed)
__device__ float g_q[(size_t)NTOK * HH * HD];    // 32 MB
__device__ float g_k[(size_t)NTOK * KVH * HD];   // 8 MB
__device__ float g_v[(size_t)NTOK * KVH * HD];   // 8 MB
__device__ float g_att[(size_t)NTOK * HH * HD];  // 32 MB

// ---------------------------------------------------------------------------
// Classic 128x128x8 register-blocked SGEMM (row-major A[MxK], B[KxN], C[MxN])
// 256 threads, 8x8 microtile. Dims assumed divisible (they are: 4096/2048/512).
// ---------------------------------------------------------------------------
__global__ __launch_bounds__(256) void sgemm128(
    int M, int N, int K,
    const float* __restrict__ A, const float* __restrict__ B,
    float* __restrict__ C)
{
    constexpr int BM = 128, BN = 128, BK = 8, TM = 8, TN = 8;
    __shared__ float As[BK][BM];   // transposed A tile
    __shared__ float Bs[BK][BN];

    const int tid = threadIdx.x;
    const int m0 = blockIdx.y * BM;
    const int n0 = blockIdx.x * BN;

    // A tile load mapping: 128 rows x 8 cols = 256 float4
    const int arow = tid >> 1;
    const int acol = (tid & 1) << 2;
    // B tile load mapping: 8 rows x 128 cols = 256 float4
    const int brl = tid >> 5;
    const int bcl = (tid & 31) << 2;
    // compute mapping: 16x16 threads, 8x8 each
    const int tr = (tid >> 4) * TM;
    const int tc = (tid & 15) * TN;

    float acc[TM][TN];
    #pragma unroll
    for (int i = 0; i < TM; i++)
        #pragma unroll
        for (int j = 0; j < TN; j++) acc[i][j] = 0.f;

    for (int k0 = 0; k0 < K; k0 += BK) {
        float4 av = *(const float4*)(A + (size_t)(m0 + arow) * K + k0 + acol);
        As[acol + 0][arow] = av.x;
        As[acol + 1][arow] = av.y;
        As[acol + 2][arow] = av.z;
        As[acol + 3][arow] = av.w;
        *(float4*)&Bs[brl][bcl] =
            *(const float4*)(B + (size_t)(k0 + brl) * N + n0 + bcl);
        __syncthreads();

        #pragma unroll
        for (int k = 0; k < BK; k++) {
            float ra[TM], rb[TN];
            #pragma unroll
            for (int i = 0; i < TM; i++) ra[i] = As[k][tr + i];
            #pragma unroll
            for (int j = 0; j < TN; j++) rb[j] = Bs[k][tc + j];
            #pragma unroll
            for (int i = 0; i < TM; i++)
                #pragma unroll
                for (int j = 0; j < TN; j++)
                    acc[i][j] = fmaf(ra[i], rb[j], acc[i][j]);
        }
        __syncthreads();
    }

    #pragma unroll
    for (int i = 0; i < TM; i++) {
        float* crow = C + (size_t)(m0 + tr + i) * N + n0 + tc;
        *(float4*)(crow + 0) = make_float4(acc[i][0], acc[i][1], acc[i][2], acc[i][3]);
        *(float4*)(crow + 4) = make_float4(acc[i][4], acc[i][5], acc[i][6], acc[i][7]);
    }
}

// ---------------------------------------------------------------------------
// Fused RMSNorm + RoPE, in place on u[NTOK][heads][HD].
// grid = NTOK blocks, block = (32, heads). One warp per head; each lane owns
// 4 consecutive dims = 2 complete (even,odd) RoPE pairs.
// ---------------------------------------------------------------------------
__global__ void rmsnorm_rope(float* __restrict__ u, const float* __restrict__ w,
                             const float* __restrict__ fc, const float* __restrict__ fs,
                             int heads)
{
    const int token = blockIdx.x;
    const int t = token & (TT - 1);          // token = b*T + t, T power of 2
    const int head = threadIdx.y;
    const int lane = threadIdx.x;

    float* base = u + ((size_t)token * heads + head) * HD;
    float4 v = *(float4*)(base + lane * 4);

    float ss = v.x * v.x + v.y * v.y + v.z * v.z + v.w * v.w;
    #pragma unroll
    for (int o = 16; o > 0; o >>= 1) ss += __shfl_xor_sync(0xFFFFFFFFu, ss, o);
    const float r = rsqrtf(ss * (1.f / HD) + 1e-6f);

    const float4 wv = *(const float4*)(w + lane * 4);
    const int p = lane * 2;                  // pair index (of 64)
    const float c0 = fc[t * (HD / 2) + p],     s0 = fs[t * (HD / 2) + p];
    const float c1 = fc[t * (HD / 2) + p + 1], s1 = fs[t * (HD / 2) + p + 1];

    const float e0 = v.x * r * wv.x, o0 = v.y * r * wv.y;
    const float e1 = v.z * r * wv.z, o1 = v.w * r * wv.w;

    float4 out;
    out.x = e0 * c0 - o0 * s0;
    out.y = e0 * s0 + o0 * c0;
    out.z = e1 * c1 - o1 * s1;
    out.w = e1 * s1 + o1 * c1;
    *(float4*)(base + lane * 4) = out;
}

// ---------------------------------------------------------------------------
// Causal flash attention (fp32, online softmax).
// Tiles: 64 q-rows x 64 k-rows, HD=128. 256 threads.
//  - Score phase: each thread computes a 4x4 S microtile (register reuse 4x).
//  - Softmax/PV: thread t owns row t/4, cols [ (t%4)*32, +32 ).
// grid = (T/64, H, B). Dynamic smem ~112 KB -> 1 block/SM.
// ---------------------------------------------------------------------------
#define FA_TQ 64
#define FA_TK 64
#define FA_SMEM ((3 * FA_TQ * HD + FA_TQ * (FA_TK + 1)) * (int)sizeof(float))

__global__ __launch_bounds__(256) void flash_kernel(
    const float* __restrict__ q, const float* __restrict__ k,
    const float* __restrict__ v, float* __restrict__ o)
{
    extern __shared__ float sm[];
    float* Qs = sm;                      // [64][128]
    float* Ks = Qs + FA_TQ * HD;         // [64][128]
    float* Vs = Ks + FA_TK * HD;         // [64][128]
    float* Ss = Vs + FA_TK * HD;         // [64][65]

    const int qt = blockIdx.x;
    const int h  = blockIdx.y;
    const int b  = blockIdx.z;
    const int g  = h / REP;
    const int tid = threadIdx.x;
    const int q0 = qt * FA_TQ;

    // Load Q tile (coalesced float4)
    for (int i = tid; i < FA_TQ * (HD / 4); i += 256) {
        int r = i / (HD / 4), c4 = i % (HD / 4);
        ((float4*)Qs)[r * (HD / 4) + c4] =
            *(const float4*)(q + (((size_t)(b * TT + q0 + r) * HH + h) * HD) + c4 * 4);
    }

    // Score microtile mapping
    const int sr = (tid >> 4) * 4;       // 0..60
    const int sc = (tid & 15) * 4;       // 0..60
    // Softmax/PV mapping
    const int row = tid >> 2;            // 0..63
    const int cg  = tid & 3;             // 0..3 (32-col group)

    float acc[32];
    #pragma unroll
    for (int j = 0; j < 32; j++) acc[j] = 0.f;
    float m = -1e30f, l = 0.f;

    const float scale = 0.08838834764831845f;  // 1/sqrt(128)

    for (int kt = 0; kt <= qt; kt++) {
        const int k0 = kt * FA_TK;
        __syncthreads();  // protects Qs on iter0; Ss/Vs consumers before overwrite

        for (int i = tid; i < FA_TK * (HD / 4); i += 256) {
            int r = i / (HD / 4), c4 = i % (HD / 4);
            size_t gidx = (((size_t)(b * TT + k0 + r) * KVH + g) * HD) + c4 * 4;
            ((float4*)Ks)[i] = *(const float4*)(k + gidx);
            ((float4*)Vs)[i] = *(const float4*)(v + gidx);
        }
        __syncthreads();

        // --- scores: 4x4 microtile per thread ---
        float sacc[4][4];
        #pragma unroll
        for (int i = 0; i < 4; i++)
            #pragma unroll
            for (int j = 0; j < 4; j++) sacc[i][j] = 0.f;

        const float4* Q4 = (const float4*)Qs;
        const float4* K4 = (const float4*)Ks;
        #pragma unroll 8
        for (int kk = 0; kk < HD / 4; kk++) {
            float4 qa[4], kb[4];
            #pragma unroll
            for (int i = 0; i < 4; i++) qa[i] = Q4[(sr + i) * (HD / 4) + kk];
            #pragma unroll
            for (int j = 0; j < 4; j++) kb[j] = K4[(sc + j) * (HD / 4) + kk];
            #pragma unroll
            for (int i = 0; i < 4; i++)
                #pragma unroll
                for (int j = 0; j < 4; j++)
                    sacc[i][j] += qa[i].x * kb[j].x + qa[i].y * kb[j].y +
                                  qa[i].z * kb[j].z + qa[i].w * kb[j].w;
        }
        const bool diag = (kt == qt);
        #pragma unroll
        for (int i = 0; i < 4; i++)
            #pragma unroll
            for (int j = 0; j < 4; j++) {
                int r = sr + i, c = sc + j;
                float s = sacc[i][j] * scale;
                if (diag && c > r) s = -1e30f;
                Ss[r * (FA_TK + 1) + c] = s;
            }
        __syncthreads();

        // --- online softmax + PV ---
        const float* srow = Ss + row * (FA_TK + 1);
        float rowmax = -1e30f;
        #pragma unroll 8
        for (int c = 0; c < FA_TK; c++) rowmax = fmaxf(rowmax, srow[c]);
        const float newm = fmaxf(m, rowmax);
        const float corr = __expf(m - newm);
        l *= corr;
        #pragma unroll
        for (int j = 0; j < 32; j++) acc[j] *= corr;

        for (int c = 0; c < FA_TK; c++) {
            const float p = __expf(srow[c] - newm);
            l += p;
            const float4* vr = (const float4*)(Vs + c * HD + cg * 32);
            #pragma unroll
            for (int j4 = 0; j4 < 8; j4++) {
                float4 vv = vr[j4];
                acc[j4 * 4 + 0] += p * vv.x;
                acc[j4 * 4 + 1] += p * vv.y;
                acc[j4 * 4 + 2] += p * vv.z;
                acc[j4 * 4 + 3] += p * vv.w;
            }
        }
        m = newm;
    }

    const float rl = 1.f / l;
    float* ob = o + (((size_t)(b * TT + q0 + row) * HH + h) * HD) + cg * 32;
    #pragma unroll
    for (int j4 = 0; j4 < 8; j4++) {
        float4 ov = make_float4(acc[j4 * 4 + 0] * rl, acc[j4 * 4 + 1] * rl,
                                acc[j4 * 4 + 2] * rl, acc[j4 * 4 + 3] * rl);
        *(float4*)(ob + j4 * 4) = ov;
    }
}

// ---------------------------------------------------------------------------
extern "C" void kernel_launch(void* const* d_in, const int* in_sizes, int n_in,
                              void* d_out, int out_size)
{
    const float* x    = (const float*)d_in[0];
    const float* wq   = (const float*)d_in[1];
    const float* wk   = (const float*)d_in[2];
    const float* wv   = (const float*)d_in[3];
    const float* wo   = (const float*)d_in[4];
    const float* qnw  = (const float*)d_in[5];
    const float* knw  = (const float*)d_in[6];
    const float* fcos = (const float*)d_in[7];
    const float* fsin = (const float*)d_in[8];
    float* out = (float*)d_out;

    float *q, *k, *v, *att;
    cudaGetSymbolAddress((void**)&q,   g_q);
    cudaGetSymbolAddress((void**)&k,   g_k);
    cudaGetSymbolAddress((void**)&v,   g_v);
    cudaGetSymbolAddress((void**)&att, g_att);

    // Projections
    sgemm128<<<dim3((HH * HD) / 128, NTOK / 128), 256>>>(NTOK, HH * HD, DD, x, wq, q);
    sgemm128<<<dim3((KVH * HD) / 128, NTOK / 128), 256>>>(NTOK, KVH * HD, DD, x, wk, k);
    sgemm128<<<dim3((KVH * HD) / 128, NTOK / 128), 256>>>(NTOK, KVH * HD, DD, x, wv, v);

    // RMSNorm + RoPE (in place)
    rmsnorm_rope<<<NTOK, dim3(32, HH)>>>(q, qnw, fcos, fsin, HH);
    rmsnorm_rope<<<NTOK, dim3(32, KVH)>>>(k, knw, fcos, fsin, KVH);

    // Flash attention
    cudaFuncSetAttribute(flash_kernel, cudaFuncAttributeMaxDynamicSharedMemorySize, FA_SMEM);
    flash_kernel<<<dim3(TT / FA_TQ, HH, BB), 256, FA_SMEM>>>(q, k, v, att);

    // Output projection
    sgemm128<<<dim3(DD / 128, NTOK / 128), 256>>>(NTOK, DD, HH * HD, att, wo, out);
}

// round 5
// speedup vs baseline: 1.2221x; 1.2221x over previous
#include <cuda_runtime.h>
#include <cuda_bf16.h>
#include <math.h>
#include <cstdint>

// Problem constants
#define BB 2
#define TT 2048
#define DD 2048
#define HH 16
#define KVH 4
#define HD 128
#define REP (HH / KVH)
#define NTOK (BB * TT)   // 4096

// Scratch (device globals — no allocation allowed)
__device__ float g_q[(size_t)NTOK * HH * HD];    // 32 MB
__device__ float g_k[(size_t)NTOK * KVH * HD];   // 8 MB
__device__ float g_v[(size_t)NTOK * KVH * HD];   // 8 MB
__device__ float g_att[(size_t)NTOK * HH * HD];  // 32 MB

__device__ __forceinline__ uint32_t f2tf32(float f) {
    uint32_t r;
    asm("cvt.rna.tf32.f32 %0, %1;" : "=r"(r) : "f"(f));
    return r;
}

__device__ __forceinline__ void mma_tf32(float c[4],
    uint32_t a0, uint32_t a1, uint32_t a2, uint32_t a3,
    uint32_t b0, uint32_t b1)
{
    asm volatile(
        "mma.sync.aligned.m16n8k8.row.col.f32.tf32.tf32.f32 "
        "{%0,%1,%2,%3}, {%4,%5,%6,%7}, {%8,%9}, {%0,%1,%2,%3};"
        : "+f"(c[0]), "+f"(c[1]), "+f"(c[2]), "+f"(c[3])
        : "r"(a0), "r"(a1), "r"(a2), "r"(a3), "r"(b0), "r"(b1));
}

// ===========================================================================
// tf32 mma.sync GEMM: C[M,N] = A[M,K] @ B[K,N], fp32 in/out.
// 128x128 tile, BK=16, double-buffered. 8 warps (2 x 4), warp tile 64x32.
// m16n8k8 fragments; A stored row-major [128][20] (pad 4), B as [16][136].
// Requires K % 16 == 0, M % 128 == 0, N % 128 == 0.
// ===========================================================================
#define GBM 128
#define GBN 128
#define GBK 16
#define ASTR (GBK + 4)    // 20 floats
#define BSTR (GBN + 8)    // 136 floats

__global__ __launch_bounds__(256) void gemm_mma(
    int M, int N, int K,
    const float* __restrict__ A, const float* __restrict__ B,
    float* __restrict__ C)
{
    __shared__ float As[2][GBM][ASTR];
    __shared__ float Bs[2][GBK][BSTR];

    const int tid  = threadIdx.x;
    const int wid  = tid >> 5;
    const int lane = tid & 31;
    const int gid  = lane >> 2;   // 0..7
    const int tid4 = lane & 3;    // 0..3

    const int warp_m = (wid & 1) * 64;   // 0 or 64
    const int warp_n = (wid >> 1) * 32;  // 0,32,64,96

    const int m0 = blockIdx.y * GBM;
    const int n0 = blockIdx.x * GBN;

    // Global load mappings
    const int ar  = tid >> 2;     // 0..63 (also +64)
    const int ac4 = tid & 3;      // float4 col within BK16
    const int bk  = tid >> 5;     // 0..7  (also +8)
    const int bn4 = tid & 31;     // float4 col within BN128

    const float* aptr = A + (size_t)(m0 + ar) * K + ac4 * 4;
    const float* bptr = B + (size_t)bk * N + n0 + bn4 * 4;
    const size_t aoff2 = (size_t)64 * K;
    const size_t boff2 = (size_t)8 * N;

    float acc[4][4][4];
    #pragma unroll
    for (int i = 0; i < 4; i++)
        #pragma unroll
        for (int j = 0; j < 4; j++)
            #pragma unroll
            for (int r = 0; r < 4; r++) acc[i][j][r] = 0.f;

    const int nch = K / GBK;

    // Preload chunk 0
    float4 pa0 = *(const float4*)(aptr);
    float4 pa1 = *(const float4*)(aptr + aoff2);
    float4 pb0 = *(const float4*)(bptr);
    float4 pb1 = *(const float4*)(bptr + boff2);

    {   // store chunk 0 into buf 0
        uint32_t t[4];
        t[0]=f2tf32(pa0.x); t[1]=f2tf32(pa0.y); t[2]=f2tf32(pa0.z); t[3]=f2tf32(pa0.w);
        *(uint4*)&As[0][ar][ac4 * 4] = *(uint4*)t;
        t[0]=f2tf32(pa1.x); t[1]=f2tf32(pa1.y); t[2]=f2tf32(pa1.z); t[3]=f2tf32(pa1.w);
        *(uint4*)&As[0][ar + 64][ac4 * 4] = *(uint4*)t;
        t[0]=f2tf32(pb0.x); t[1]=f2tf32(pb0.y); t[2]=f2tf32(pb0.z); t[3]=f2tf32(pb0.w);
        *(uint4*)&Bs[0][bk][bn4 * 4] = *(uint4*)t;
        t[0]=f2tf32(pb1.x); t[1]=f2tf32(pb1.y); t[2]=f2tf32(pb1.z); t[3]=f2tf32(pb1.w);
        *(uint4*)&Bs[0][bk + 8][bn4 * 4] = *(uint4*)t;
    }
    __syncthreads();

    for (int ch = 0; ch < nch; ch++) {
        const int buf = ch & 1;
        const int nxt = ch + 1;

        if (nxt < nch) {
            const float* ap = aptr + (size_t)nxt * GBK;
            const float* bp = bptr + (size_t)nxt * GBK * N;
            pa0 = *(const float4*)(ap);
            pa1 = *(const float4*)(ap + aoff2);
            pb0 = *(const float4*)(bp);
            pb1 = *(const float4*)(bp + boff2);
        }

        // Compute on current buffer: 2 k-frags of 8
        #pragma unroll
        for (int kk = 0; kk < 2; kk++) {
            const int kb = kk * 8;
            uint32_t af[4][4], bf[4][2];
            #pragma unroll
            for (int mi = 0; mi < 4; mi++) {
                const int r = warp_m + mi * 16 + gid;
                af[mi][0] = __float_as_uint(As[buf][r    ][kb + tid4]);
                af[mi][1] = __float_as_uint(As[buf][r + 8][kb + tid4]);
                af[mi][2] = __float_as_uint(As[buf][r    ][kb + tid4 + 4]);
                af[mi][3] = __float_as_uint(As[buf][r + 8][kb + tid4 + 4]);
            }
            #pragma unroll
            for (int ni = 0; ni < 4; ni++) {
                const int c = warp_n + ni * 8 + gid;
                bf[ni][0] = __float_as_uint(Bs[buf][kb + tid4    ][c]);
                bf[ni][1] = __float_as_uint(Bs[buf][kb + tid4 + 4][c]);
            }
            #pragma unroll
            for (int mi = 0; mi < 4; mi++)
                #pragma unroll
                for (int ni = 0; ni < 4; ni++)
                    mma_tf32(acc[mi][ni], af[mi][0], af[mi][1], af[mi][2], af[mi][3],
                             bf[ni][0], bf[ni][1]);
        }

        if (nxt < nch) {
            const int nb = nxt & 1;
            uint32_t t[4];
            t[0]=f2tf32(pa0.x); t[1]=f2tf32(pa0.y); t[2]=f2tf32(pa0.z); t[3]=f2tf32(pa0.w);
            *(uint4*)&As[nb][ar][ac4 * 4] = *(uint4*)t;
            t[0]=f2tf32(pa1.x); t[1]=f2tf32(pa1.y); t[2]=f2tf32(pa1.z); t[3]=f2tf32(pa1.w);
            *(uint4*)&As[nb][ar + 64][ac4 * 4] = *(uint4*)t;
            t[0]=f2tf32(pb0.x); t[1]=f2tf32(pb0.y); t[2]=f2tf32(pb0.z); t[3]=f2tf32(pb0.w);
            *(uint4*)&Bs[nb][bk][bn4 * 4] = *(uint4*)t;
            t[0]=f2tf32(pb1.x); t[1]=f2tf32(pb1.y); t[2]=f2tf32(pb1.z); t[3]=f2tf32(pb1.w);
            *(uint4*)&Bs[nb][bk + 8][bn4 * 4] = *(uint4*)t;
        }
        __syncthreads();
    }

    // Epilogue: each warp writes its 64x32 tile
    #pragma unroll
    for (int mi = 0; mi < 4; mi++) {
        const int r = m0 + warp_m + mi * 16 + gid;
        #pragma unroll
        for (int ni = 0; ni < 4; ni++) {
            const int c = n0 + warp_n + ni * 8 + tid4 * 2;
            *(float2*)(C + (size_t)r * N + c) =
                make_float2(acc[mi][ni][0], acc[mi][ni][1]);
            *(float2*)(C + (size_t)(r + 8) * N + c) =
                make_float2(acc[mi][ni][2], acc[mi][ni][3]);
        }
    }
}

// ---------------------------------------------------------------------------
// Fused RMSNorm + RoPE, in place on u[NTOK][heads][HD]. (unchanged)
// ---------------------------------------------------------------------------
__global__ void rmsnorm_rope(float* __restrict__ u, const float* __restrict__ w,
                             const float* __restrict__ fc, const float* __restrict__ fs,
                             int heads)
{
    const int token = blockIdx.x;
    const int t = token & (TT - 1);
    const int head = threadIdx.y;
    const int lane = threadIdx.x;

    float* base = u + ((size_t)token * heads + head) * HD;
    float4 v = *(float4*)(base + lane * 4);

    float ss = v.x * v.x + v.y * v.y + v.z * v.z + v.w * v.w;
    #pragma unroll
    for (int o = 16; o > 0; o >>= 1) ss += __shfl_xor_sync(0xFFFFFFFFu, ss, o);
    const float r = rsqrtf(ss * (1.f / HD) + 1e-6f);

    const float4 wv = *(const float4*)(w + lane * 4);
    const int p = lane * 2;
    const float c0 = fc[t * (HD / 2) + p],     s0 = fs[t * (HD / 2) + p];
    const float c1 = fc[t * (HD / 2) + p + 1], s1 = fs[t * (HD / 2) + p + 1];

    const float e0 = v.x * r * wv.x, o0 = v.y * r * wv.y;
    const float e1 = v.z * r * wv.z, o1 = v.w * r * wv.w;

    float4 out;
    out.x = e0 * c0 - o0 * s0;
    out.y = e0 * s0 + o0 * c0;
    out.z = e1 * c1 - o1 * s1;
    out.w = e1 * s1 + o1 * c1;
    *(float4*)(base + lane * 4) = out;
}

// ---------------------------------------------------------------------------
// Causal flash attention (fp32, online softmax). (unchanged — next target)
// ---------------------------------------------------------------------------
#define FA_TQ 64
#define FA_TK 64
#define FA_SMEM ((3 * FA_TQ * HD + FA_TQ * (FA_TK + 1)) * (int)sizeof(float))

__global__ __launch_bounds__(256) void flash_kernel(
    const float* __restrict__ q, const float* __restrict__ k,
    const float* __restrict__ v, float* __restrict__ o)
{
    extern __shared__ float sm[];
    float* Qs = sm;
    float* Ks = Qs + FA_TQ * HD;
    float* Vs = Ks + FA_TK * HD;
    float* Ss = Vs + FA_TK * HD;

    const int qt = blockIdx.x;
    const int h  = blockIdx.y;
    const int b  = blockIdx.z;
    const int g  = h / REP;
    const int tid = threadIdx.x;
    const int q0 = qt * FA_TQ;

    for (int i = tid; i < FA_TQ * (HD / 4); i += 256) {
        int r = i / (HD / 4), c4 = i % (HD / 4);
        ((float4*)Qs)[r * (HD / 4) + c4] =
            *(const float4*)(q + (((size_t)(b * TT + q0 + r) * HH + h) * HD) + c4 * 4);
    }

    const int sr = (tid >> 4) * 4;
    const int sc = (tid & 15) * 4;
    const int row = tid >> 2;
    const int cg  = tid & 3;

    float acc[32];
    #pragma unroll
    for (int j = 0; j < 32; j++) acc[j] = 0.f;
    float m = -1e30f, l = 0.f;

    const float scale = 0.08838834764831845f;

    for (int kt = 0; kt <= qt; kt++) {
        const int k0 = kt * FA_TK;
        __syncthreads();

        for (int i = tid; i < FA_TK * (HD / 4); i += 256) {
            int r = i / (HD / 4), c4 = i % (HD / 4);
            size_t gidx = (((size_t)(b * TT + k0 + r) * KVH + g) * HD) + c4 * 4;
            ((float4*)Ks)[i] = *(const float4*)(k + gidx);
            ((float4*)Vs)[i] = *(const float4*)(v + gidx);
        }
        __syncthreads();

        float sacc[4][4];
        #pragma unroll
        for (int i = 0; i < 4; i++)
            #pragma unroll
            for (int j = 0; j < 4; j++) sacc[i][j] = 0.f;

        const float4* Q4 = (const float4*)Qs;
        const float4* K4 = (const float4*)Ks;
        #pragma unroll 8
        for (int kk = 0; kk < HD / 4; kk++) {
            float4 qa[4], kb[4];
            #pragma unroll
            for (int i = 0; i < 4; i++) qa[i] = Q4[(sr + i) * (HD / 4) + kk];
            #pragma unroll
            for (int j = 0; j < 4; j++) kb[j] = K4[(sc + j) * (HD / 4) + kk];
            #pragma unroll
            for (int i = 0; i < 4; i++)
                #pragma unroll
                for (int j = 0; j < 4; j++)
                    sacc[i][j] += qa[i].x * kb[j].x + qa[i].y * kb[j].y +
                                  qa[i].z * kb[j].z + qa[i].w * kb[j].w;
        }
        const bool diag = (kt == qt);
        #pragma unroll
        for (int i = 0; i < 4; i++)
            #pragma unroll
            for (int j = 0; j < 4; j++) {
                int r = sr + i, c = sc + j;
                float s = sacc[i][j] * scale;
                if (diag && c > r) s = -1e30f;
                Ss[r * (FA_TK + 1) + c] = s;
            }
        __syncthreads();

        const float* srow = Ss + row * (FA_TK + 1);
        float rowmax = -1e30f;
        #pragma unroll 8
        for (int c = 0; c < FA_TK; c++) rowmax = fmaxf(rowmax, srow[c]);
        const float newm = fmaxf(m, rowmax);
        const float corr = __expf(m - newm);
        l *= corr;
        #pragma unroll
        for (int j = 0; j < 32; j++) acc[j] *= corr;

        for (int c = 0; c < FA_TK; c++) {
            const float p = __expf(srow[c] - newm);
            l += p;
            const float4* vr = (const float4*)(Vs + c * HD + cg * 32);
            #pragma unroll
            for (int j4 = 0; j4 < 8; j4++) {
                float4 vv = vr[j4];
                acc[j4 * 4 + 0] += p * vv.x;
                acc[j4 * 4 + 1] += p * vv.y;
                acc[j4 * 4 + 2] += p * vv.z;
                acc[j4 * 4 + 3] += p * vv.w;
            }
        }
        m = newm;
    }

    const float rl = 1.f / l;
    float* ob = o + (((size_t)(b * TT + q0 + row) * HH + h) * HD) + cg * 32;
    #pragma unroll
    for (int j4 = 0; j4 < 8; j4++) {
        float4 ov = make_float4(acc[j4 * 4 + 0] * rl, acc[j4 * 4 + 1] * rl,
                                acc[j4 * 4 + 2] * rl, acc[j4 * 4 + 3] * rl);
        *(float4*)(ob + j4 * 4) = ov;
    }
}

// ---------------------------------------------------------------------------
extern "C" void kernel_launch(void* const* d_in, const int* in_sizes, int n_in,
                              void* d_out, int out_size)
{
    const float* x    = (const float*)d_in[0];
    const float* wq   = (const float*)d_in[1];
    const float* wk   = (const float*)d_in[2];
    const float* wv   = (const float*)d_in[3];
    const float* wo   = (const float*)d_in[4];
    const float* qnw  = (const float*)d_in[5];
    const float* knw  = (const float*)d_in[6];
    const float* fcos = (const float*)d_in[7];
    const float* fsin = (const float*)d_in[8];
    float* out = (float*)d_out;

    float *q, *k, *v, *att;
    cudaGetSymbolAddress((void**)&q,   g_q);
    cudaGetSymbolAddress((void**)&k,   g_k);
    cudaGetSymbolAddress((void**)&v,   g_v);
    cudaGetSymbolAddress((void**)&att, g_att);

    cudaFuncSetAttribute(flash_kernel, cudaFuncAttributeMaxDynamicSharedMemorySize, FA_SMEM);

    // Projections (tensor core tf32 via mma.sync)
    gemm_mma<<<dim3((HH * HD) / GBN, NTOK / GBM), 256>>>(NTOK, HH * HD, DD, x, wq, q);
    gemm_mma<<<dim3((KVH * HD) / GBN, NTOK / GBM), 256>>>(NTOK, KVH * HD, DD, x, wk, k);
    gemm_mma<<<dim3((KVH * HD) / GBN, NTOK / GBM), 256>>>(NTOK, KVH * HD, DD, x, wv, v);

    // RMSNorm + RoPE (in place)
    rmsnorm_rope<<<NTOK, dim3(32, HH)>>>(q, qnw, fcos, fsin, HH);
    rmsnorm_rope<<<NTOK, dim3(32, KVH)>>>(k, knw, fcos, fsin, KVH);

    // Flash attention
    flash_kernel<<<dim3(TT / FA_TQ, HH, BB), 256, FA_SMEM>>>(q, k, v, att);

    // Output projection
    gemm_mma<<<dim3(DD / GBN, NTOK / GBM), 256>>>(NTOK, DD, HH * HD, att, wo, out);
}

// round 6
// speedup vs baseline: 7.6879x; 6.2907x over previous
#include <cuda_runtime.h>
#include <cuda_bf16.h>
#include <math.h>
#include <cstdint>

// Problem constants
#define BB 2
#define TT 2048
#define DD 2048
#define HH 16
#define KVH 4
#define HD 128
#define REP (HH / KVH)
#define NTOK (BB * TT)   // 4096

// Scratch (device globals — no allocation allowed)
__device__ float g_q[(size_t)NTOK * HH * HD];    // 32 MB
__device__ float g_k[(size_t)NTOK * KVH * HD];   // 8 MB
__device__ float g_v[(size_t)NTOK * KVH * HD];   // 8 MB
__device__ float g_att[(size_t)NTOK * HH * HD];  // 32 MB

__device__ __forceinline__ uint32_t f2tf32(float f) {
    uint32_t r;
    asm("cvt.rna.tf32.f32 %0, %1;" : "=r"(r) : "f"(f));
    return r;
}

__device__ __forceinline__ void mma_tf32(float c[4],
    uint32_t a0, uint32_t a1, uint32_t a2, uint32_t a3,
    uint32_t b0, uint32_t b1)
{
    asm volatile(
        "mma.sync.aligned.m16n8k8.row.col.f32.tf32.tf32.f32 "
        "{%0,%1,%2,%3}, {%4,%5,%6,%7}, {%8,%9}, {%0,%1,%2,%3};"
        : "+f"(c[0]), "+f"(c[1]), "+f"(c[2]), "+f"(c[3])
        : "r"(a0), "r"(a1), "r"(a2), "r"(a3), "r"(b0), "r"(b1));
}

// ===========================================================================
// tf32 mma.sync GEMM (unchanged from R5 — passing)
// ===========================================================================
#define GBM 128
#define GBN 128
#define GBK 16
#define ASTR (GBK + 4)
#define BSTR (GBN + 8)

__global__ __launch_bounds__(256) void gemm_mma(
    int M, int N, int K,
    const float* __restrict__ A, const float* __restrict__ B,
    float* __restrict__ C)
{
    __shared__ float As[2][GBM][ASTR];
    __shared__ float Bs[2][GBK][BSTR];

    const int tid  = threadIdx.x;
    const int wid  = tid >> 5;
    const int lane = tid & 31;
    const int gid  = lane >> 2;
    const int tid4 = lane & 3;

    const int warp_m = (wid & 1) * 64;
    const int warp_n = (wid >> 1) * 32;

    const int m0 = blockIdx.y * GBM;
    const int n0 = blockIdx.x * GBN;

    const int ar  = tid >> 2;
    const int ac4 = tid & 3;
    const int bk  = tid >> 5;
    const int bn4 = tid & 31;

    const float* aptr = A + (size_t)(m0 + ar) * K + ac4 * 4;
    const float* bptr = B + (size_t)bk * N + n0 + bn4 * 4;
    const size_t aoff2 = (size_t)64 * K;
    const size_t boff2 = (size_t)8 * N;

    float acc[4][4][4];
    #pragma unroll
    for (int i = 0; i < 4; i++)
        #pragma unroll
        for (int j = 0; j < 4; j++)
            #pragma unroll
            for (int r = 0; r < 4; r++) acc[i][j][r] = 0.f;

    const int nch = K / GBK;

    float4 pa0 = *(const float4*)(aptr);
    float4 pa1 = *(const float4*)(aptr + aoff2);
    float4 pb0 = *(const float4*)(bptr);
    float4 pb1 = *(const float4*)(bptr + boff2);

    {
        uint32_t t[4];
        t[0]=f2tf32(pa0.x); t[1]=f2tf32(pa0.y); t[2]=f2tf32(pa0.z); t[3]=f2tf32(pa0.w);
        *(uint4*)&As[0][ar][ac4 * 4] = *(uint4*)t;
        t[0]=f2tf32(pa1.x); t[1]=f2tf32(pa1.y); t[2]=f2tf32(pa1.z); t[3]=f2tf32(pa1.w);
        *(uint4*)&As[0][ar + 64][ac4 * 4] = *(uint4*)t;
        t[0]=f2tf32(pb0.x); t[1]=f2tf32(pb0.y); t[2]=f2tf32(pb0.z); t[3]=f2tf32(pb0.w);
        *(uint4*)&Bs[0][bk][bn4 * 4] = *(uint4*)t;
        t[0]=f2tf32(pb1.x); t[1]=f2tf32(pb1.y); t[2]=f2tf32(pb1.z); t[3]=f2tf32(pb1.w);
        *(uint4*)&Bs[0][bk + 8][bn4 * 4] = *(uint4*)t;
    }
    __syncthreads();

    for (int ch = 0; ch < nch; ch++) {
        const int buf = ch & 1;
        const int nxt = ch + 1;

        if (nxt < nch) {
            const float* ap = aptr + (size_t)nxt * GBK;
            const float* bp = bptr + (size_t)nxt * GBK * N;
            pa0 = *(const float4*)(ap);
            pa1 = *(const float4*)(ap + aoff2);
            pb0 = *(const float4*)(bp);
            pb1 = *(const float4*)(bp + boff2);
        }

        #pragma unroll
        for (int kk = 0; kk < 2; kk++) {
            const int kb = kk * 8;
            uint32_t af[4][4], bf[4][2];
            #pragma unroll
            for (int mi = 0; mi < 4; mi++) {
                const int r = warp_m + mi * 16 + gid;
                af[mi][0] = __float_as_uint(As[buf][r    ][kb + tid4]);
                af[mi][1] = __float_as_uint(As[buf][r + 8][kb + tid4]);
                af[mi][2] = __float_as_uint(As[buf][r    ][kb + tid4 + 4]);
                af[mi][3] = __float_as_uint(As[buf][r + 8][kb + tid4 + 4]);
            }
            #pragma unroll
            for (int ni = 0; ni < 4; ni++) {
                const int c = warp_n + ni * 8 + gid;
                bf[ni][0] = __float_as_uint(Bs[buf][kb + tid4    ][c]);
                bf[ni][1] = __float_as_uint(Bs[buf][kb + tid4 + 4][c]);
            }
            #pragma unroll
            for (int mi = 0; mi < 4; mi++)
                #pragma unroll
                for (int ni = 0; ni < 4; ni++)
                    mma_tf32(acc[mi][ni], af[mi][0], af[mi][1], af[mi][2], af[mi][3],
                             bf[ni][0], bf[ni][1]);
        }

        if (nxt < nch) {
            const int nb = nxt & 1;
            uint32_t t[4];
            t[0]=f2tf32(pa0.x); t[1]=f2tf32(pa0.y); t[2]=f2tf32(pa0.z); t[3]=f2tf32(pa0.w);
            *(uint4*)&As[nb][ar][ac4 * 4] = *(uint4*)t;
            t[0]=f2tf32(pa1.x); t[1]=f2tf32(pa1.y); t[2]=f2tf32(pa1.z); t[3]=f2tf32(pa1.w);
            *(uint4*)&As[nb][ar + 64][ac4 * 4] = *(uint4*)t;
            t[0]=f2tf32(pb0.x); t[1]=f2tf32(pb0.y); t[2]=f2tf32(pb0.z); t[3]=f2tf32(pb0.w);
            *(uint4*)&Bs[nb][bk][bn4 * 4] = *(uint4*)t;
            t[0]=f2tf32(pb1.x); t[1]=f2tf32(pb1.y); t[2]=f2tf32(pb1.z); t[3]=f2tf32(pb1.w);
            *(uint4*)&Bs[nb][bk + 8][bn4 * 4] = *(uint4*)t;
        }
        __syncthreads();
    }

    #pragma unroll
    for (int mi = 0; mi < 4; mi++) {
        const int r = m0 + warp_m + mi * 16 + gid;
        #pragma unroll
        for (int ni = 0; ni < 4; ni++) {
            const int c = n0 + warp_n + ni * 8 + tid4 * 2;
            *(float2*)(C + (size_t)r * N + c) =
                make_float2(acc[mi][ni][0], acc[mi][ni][1]);
            *(float2*)(C + (size_t)(r + 8) * N + c) =
                make_float2(acc[mi][ni][2], acc[mi][ni][3]);
        }
    }
}

// ---------------------------------------------------------------------------
// Fused RMSNorm + RoPE (unchanged)
// ---------------------------------------------------------------------------
__global__ void rmsnorm_rope(float* __restrict__ u, const float* __restrict__ w,
                             const float* __restrict__ fc, const float* __restrict__ fs,
                             int heads)
{
    const int token = blockIdx.x;
    const int t = token & (TT - 1);
    const int head = threadIdx.y;
    const int lane = threadIdx.x;

    float* base = u + ((size_t)token * heads + head) * HD;
    float4 v = *(float4*)(base + lane * 4);

    float ss = v.x * v.x + v.y * v.y + v.z * v.z + v.w * v.w;
    #pragma unroll
    for (int o = 16; o > 0; o >>= 1) ss += __shfl_xor_sync(0xFFFFFFFFu, ss, o);
    const float r = rsqrtf(ss * (1.f / HD) + 1e-6f);

    const float4 wv = *(const float4*)(w + lane * 4);
    const int p = lane * 2;
    const float c0 = fc[t * (HD / 2) + p],     s0 = fs[t * (HD / 2) + p];
    const float c1 = fc[t * (HD / 2) + p + 1], s1 = fs[t * (HD / 2) + p + 1];

    const float e0 = v.x * r * wv.x, o0 = v.y * r * wv.y;
    const float e1 = v.z * r * wv.z, o1 = v.w * r * wv.w;

    float4 out;
    out.x = e0 * c0 - o0 * s0;
    out.y = e0 * s0 + o0 * c0;
    out.z = e1 * c1 - o1 * s1;
    out.w = e1 * s1 + o1 * c1;
    *(float4*)(base + lane * 4) = out;
}

// ===========================================================================
// Tensor-core causal flash attention (tf32 mma.sync, online softmax).
// TQ=128 (8 warps x m16), TK=64. 1 CTA/SM (174KB smem).
// Fragment layouts identical to gemm_mma (verified passing).
// ===========================================================================
#define FTQ 128
#define FTK 64
#define QSTR 136
#define KSTR 136
#define PSTR 68
#define FA2_SMEM ((FTQ * QSTR + 2 * FTK * KSTR + FTQ * PSTR) * (int)sizeof(float))

__device__ __forceinline__ float redmax4(float x) {
    x = fmaxf(x, __shfl_xor_sync(0xFFFFFFFFu, x, 1));
    x = fmaxf(x, __shfl_xor_sync(0xFFFFFFFFu, x, 2));
    return x;
}
__device__ __forceinline__ float redsum4(float x) {
    x += __shfl_xor_sync(0xFFFFFFFFu, x, 1);
    x += __shfl_xor_sync(0xFFFFFFFFu, x, 2);
    return x;
}

__global__ __launch_bounds__(256) void flash_tc(
    const float* __restrict__ q, const float* __restrict__ k,
    const float* __restrict__ v, float* __restrict__ o)
{
    extern __shared__ float sm[];
    float* Qs = sm;                       // [128][136] tf32
    float* Ks = Qs + FTQ * QSTR;          // [64][136]
    float* Vs = Ks + FTK * KSTR;          // [64][136]
    float* Ps = Vs + FTK * KSTR;          // [128][68]

    const int qt = blockIdx.x;
    const int h  = blockIdx.y;
    const int b  = blockIdx.z;
    const int g  = h / REP;
    const int tid  = threadIdx.x;
    const int wid  = tid >> 5;
    const int lane = tid & 31;
    const int gid  = lane >> 2;
    const int tid4 = lane & 3;
    const int q0 = qt * FTQ;
    const int wq = wid * 16;              // warp q-row base within tile

    // Load Q tile once (fp32 -> tf32)
    #pragma unroll 4
    for (int i = tid; i < FTQ * 32; i += 256) {
        const int r = i >> 5, c4 = i & 31;
        const float4 qv = *(const float4*)(q + ((size_t)(b * TT + q0 + r) * HH + h) * HD + c4 * 4);
        uint32_t t[4] = {f2tf32(qv.x), f2tf32(qv.y), f2tf32(qv.z), f2tf32(qv.w)};
        *(uint4*)&Qs[r * QSTR + c4 * 4] = *(uint4*)t;
    }

    float oacc[16][4];
    #pragma unroll
    for (int i = 0; i < 16; i++)
        #pragma unroll
        for (int j = 0; j < 4; j++) oacc[i][j] = 0.f;
    float m0r = -1e30f, m1r = -1e30f, l0r = 0.f, l1r = 0.f;

    const float scale = 0.08838834764831845f;  // 1/sqrt(128)
    const int r0 = q0 + wq + gid;
    const int r1 = r0 + 8;
    const int nkt = 2 * qt + 2;

    for (int kt = 0; kt < nkt; kt++) {
        const int k0 = kt * FTK;
        __syncthreads();  // prev PV consumers done with Ks/Vs/Ps

        // Load K,V tiles (fp32 -> tf32)
        #pragma unroll 2
        for (int i = tid; i < FTK * 32; i += 256) {
            const int r = i >> 5, c4 = i & 31;
            const size_t gbase = ((size_t)(b * TT + k0 + r) * KVH + g) * HD + c4 * 4;
            const float4 kv = *(const float4*)(k + gbase);
            const float4 vv = *(const float4*)(v + gbase);
            uint32_t t[4] = {f2tf32(kv.x), f2tf32(kv.y), f2tf32(kv.z), f2tf32(kv.w)};
            *(uint4*)&Ks[r * KSTR + c4 * 4] = *(uint4*)t;
            uint32_t u[4] = {f2tf32(vv.x), f2tf32(vv.y), f2tf32(vv.z), f2tf32(vv.w)};
            *(uint4*)&Vs[r * KSTR + c4 * 4] = *(uint4*)u;
        }
        __syncthreads();

        // --- S = Q K^T : 8 n-tiles x 16 k-frags ---
        float sacc[8][4];
        #pragma unroll
        for (int nt = 0; nt < 8; nt++)
            #pragma unroll
            for (int j = 0; j < 4; j++) sacc[nt][j] = 0.f;

        #pragma unroll
        for (int kf = 0; kf < 16; kf++) {
            const int kb = kf * 8;
            const uint32_t a0 = __float_as_uint(Qs[(wq + gid) * QSTR + kb + tid4]);
            const uint32_t a1 = __float_as_uint(Qs[(wq + gid + 8) * QSTR + kb + tid4]);
            const uint32_t a2 = __float_as_uint(Qs[(wq + gid) * QSTR + kb + tid4 + 4]);
            const uint32_t a3 = __float_as_uint(Qs[(wq + gid + 8) * QSTR + kb + tid4 + 4]);
            #pragma unroll
            for (int nt = 0; nt < 8; nt++) {
                const uint32_t b0 = __float_as_uint(Ks[(nt * 8 + gid) * KSTR + kb + tid4]);
                const uint32_t b1 = __float_as_uint(Ks[(nt * 8 + gid) * KSTR + kb + tid4 + 4]);
                mma_tf32(sacc[nt], a0, a1, a2, a3, b0, b1);
            }
        }

        // --- scale + causal mask + row max ---
        float mn0 = m0r, mn1 = m1r;
        #pragma unroll
        for (int nt = 0; nt < 8; nt++) {
            const int c = k0 + nt * 8 + tid4 * 2;
            float s0 = sacc[nt][0] * scale, s1 = sacc[nt][1] * scale;
            float s2 = sacc[nt][2] * scale, s3 = sacc[nt][3] * scale;
            if (c     > r0) s0 = -1e30f;
            if (c + 1 > r0) s1 = -1e30f;
            if (c     > r1) s2 = -1e30f;
            if (c + 1 > r1) s3 = -1e30f;
            sacc[nt][0] = s0; sacc[nt][1] = s1; sacc[nt][2] = s2; sacc[nt][3] = s3;
            mn0 = fmaxf(mn0, fmaxf(s0, s1));
            mn1 = fmaxf(mn1, fmaxf(s2, s3));
        }
        mn0 = redmax4(mn0);
        mn1 = redmax4(mn1);

        // --- online softmax: rescale, exp, write P (tf32) ---
        const float corr0 = __expf(m0r - mn0);
        const float corr1 = __expf(m1r - mn1);
        float ps0 = 0.f, ps1 = 0.f;
        #pragma unroll
        for (int nt = 0; nt < 8; nt++) {
            const float p0 = __expf(sacc[nt][0] - mn0);
            const float p1 = __expf(sacc[nt][1] - mn0);
            const float p2 = __expf(sacc[nt][2] - mn1);
            const float p3 = __expf(sacc[nt][3] - mn1);
            ps0 += p0 + p1;
            ps1 += p2 + p3;
            const int cc = nt * 8 + 2 * tid4;
            *(float2*)&Ps[(wq + gid) * PSTR + cc] =
                make_float2(__uint_as_float(f2tf32(p0)), __uint_as_float(f2tf32(p1)));
            *(float2*)&Ps[(wq + gid + 8) * PSTR + cc] =
                make_float2(__uint_as_float(f2tf32(p2)), __uint_as_float(f2tf32(p3)));
        }
        l0r = l0r * corr0 + redsum4(ps0);
        l1r = l1r * corr1 + redsum4(ps1);
        m0r = mn0; m1r = mn1;

        #pragma unroll
        for (int nt = 0; nt < 16; nt++) {
            oacc[nt][0] *= corr0; oacc[nt][1] *= corr0;
            oacc[nt][2] *= corr1; oacc[nt][3] *= corr1;
        }
        __syncwarp();  // P rows are warp-private; make STS visible to lanes

        // --- O += P V : 16 n-tiles x 8 k-frags ---
        #pragma unroll
        for (int kf = 0; kf < 8; kf++) {
            const int kb = kf * 8;
            const uint32_t a0 = __float_as_uint(Ps[(wq + gid) * PSTR + kb + tid4]);
            const uint32_t a1 = __float_as_uint(Ps[(wq + gid + 8) * PSTR + kb + tid4]);
            const uint32_t a2 = __float_as_uint(Ps[(wq + gid) * PSTR + kb + tid4 + 4]);
            const uint32_t a3 = __float_as_uint(Ps[(wq + gid + 8) * PSTR + kb + tid4 + 4]);
            #pragma unroll
            for (int nt = 0; nt < 16; nt++) {
                const uint32_t b0 = __float_as_uint(Vs[(kb + tid4) * KSTR + nt * 8 + gid]);
                const uint32_t b1 = __float_as_uint(Vs[(kb + tid4 + 4) * KSTR + nt * 8 + gid]);
                mma_tf32(oacc[nt], a0, a1, a2, a3, b0, b1);
            }
        }
    }

    // Epilogue: normalize and store
    const float rl0 = 1.f / l0r;
    const float rl1 = 1.f / l1r;
    float* ob0 = o + ((size_t)(b * TT + r0) * HH + h) * HD;
    float* ob1 = o + ((size_t)(b * TT + r1) * HH + h) * HD;
    #pragma unroll
    for (int nt = 0; nt < 16; nt++) {
        const int c = nt * 8 + 2 * tid4;
        *(float2*)(ob0 + c) = make_float2(oacc[nt][0] * rl0, oacc[nt][1] * rl0);
        *(float2*)(ob1 + c) = make_float2(oacc[nt][2] * rl1, oacc[nt][3] * rl1);
    }
}

// ---------------------------------------------------------------------------
extern "C" void kernel_launch(void* const* d_in, const int* in_sizes, int n_in,
                              void* d_out, int out_size)
{
    const float* x    = (const float*)d_in[0];
    const float* wq   = (const float*)d_in[1];
    const float* wk   = (const float*)d_in[2];
    const float* wv   = (const float*)d_in[3];
    const float* wo   = (const float*)d_in[4];
    const float* qnw  = (const float*)d_in[5];
    const float* knw  = (const float*)d_in[6];
    const float* fcos = (const float*)d_in[7];
    const float* fsin = (const float*)d_in[8];
    float* out = (float*)d_out;

    float *q, *k, *v, *att;
    cudaGetSymbolAddress((void**)&q,   g_q);
    cudaGetSymbolAddress((void**)&k,   g_k);
    cudaGetSymbolAddress((void**)&v,   g_v);
    cudaGetSymbolAddress((void**)&att, g_att);

    cudaFuncSetAttribute(flash_tc, cudaFuncAttributeMaxDynamicSharedMemorySize, FA2_SMEM);

    // Projections (tensor core tf32 via mma.sync)
    gemm_mma<<<dim3((HH * HD) / GBN, NTOK / GBM), 256>>>(NTOK, HH * HD, DD, x, wq, q);
    gemm_mma<<<dim3((KVH * HD) / GBN, NTOK / GBM), 256>>>(NTOK, KVH * HD, DD, x, wk, k);
    gemm_mma<<<dim3((KVH * HD) / GBN, NTOK / GBM), 256>>>(NTOK, KVH * HD, DD, x, wv, v);

    // RMSNorm + RoPE (in place)
    rmsnorm_rope<<<NTOK, dim3(32, HH)>>>(q, qnw, fcos, fsin, HH);
    rmsnorm_rope<<<NTOK, dim3(32, KVH)>>>(k, knw, fcos, fsin, KVH);

    // Tensor-core flash attention
    flash_tc<<<dim3(TT / FTQ, HH, BB), 256, FA2_SMEM>>>(q, k, v, att);

    // Output projection
    gemm_mma<<<dim3(DD / GBN, NTOK / GBM), 256>>>(NTOK, DD, HH * HD, att, wo, out);
}

// round 7
// speedup vs baseline: 9.0786x; 1.1809x over previous
#include <cuda_runtime.h>
#include <cuda_bf16.h>
#include <math.h>
#include <cstdint>

// Problem constants
#define BB 2
#define TT 2048
#define DD 2048
#define HH 16
#define KVH 4
#define HD 128
#define REP (HH / KVH)
#define NTOK (BB * TT)   // 4096

// Scratch (device globals — no allocation allowed)
__device__ float g_q[(size_t)NTOK * HH * HD];    // 32 MB
__device__ float g_k[(size_t)NTOK * KVH * HD];   // 8 MB
__device__ float g_v[(size_t)NTOK * KVH * HD];   // 8 MB
__device__ float g_att[(size_t)NTOK * HH * HD];  // 32 MB

__device__ __forceinline__ uint32_t f2tf32(float f) {
    uint32_t r;
    asm("cvt.rna.tf32.f32 %0, %1;" : "=r"(r) : "f"(f));
    return r;
}

__device__ __forceinline__ void mma_tf32(float c[4],
    uint32_t a0, uint32_t a1, uint32_t a2, uint32_t a3,
    uint32_t b0, uint32_t b1)
{
    asm volatile(
        "mma.sync.aligned.m16n8k8.row.col.f32.tf32.tf32.f32 "
        "{%0,%1,%2,%3}, {%4,%5,%6,%7}, {%8,%9}, {%0,%1,%2,%3};"
        : "+f"(c[0]), "+f"(c[1]), "+f"(c[2]), "+f"(c[3])
        : "r"(a0), "r"(a1), "r"(a2), "r"(a3), "r"(b0), "r"(b1));
}

// ===========================================================================
// tf32 mma.sync GEMM (unchanged — passing at ~307 TF/s)
// ===========================================================================
#define GBM 128
#define GBN 128
#define GBK 16
#define ASTR (GBK + 4)
#define BSTR (GBN + 8)

__global__ __launch_bounds__(256) void gemm_mma(
    int M, int N, int K,
    const float* __restrict__ A, const float* __restrict__ B,
    float* __restrict__ C)
{
    __shared__ float As[2][GBM][ASTR];
    __shared__ float Bs[2][GBK][BSTR];

    const int tid  = threadIdx.x;
    const int wid  = tid >> 5;
    const int lane = tid & 31;
    const int gid  = lane >> 2;
    const int tid4 = lane & 3;

    const int warp_m = (wid & 1) * 64;
    const int warp_n = (wid >> 1) * 32;

    const int m0 = blockIdx.y * GBM;
    const int n0 = blockIdx.x * GBN;

    const int ar  = tid >> 2;
    const int ac4 = tid & 3;
    const int bk  = tid >> 5;
    const int bn4 = tid & 31;

    const float* aptr = A + (size_t)(m0 + ar) * K + ac4 * 4;
    const float* bptr = B + (size_t)bk * N + n0 + bn4 * 4;
    const size_t aoff2 = (size_t)64 * K;
    const size_t boff2 = (size_t)8 * N;

    float acc[4][4][4];
    #pragma unroll
    for (int i = 0; i < 4; i++)
        #pragma unroll
        for (int j = 0; j < 4; j++)
            #pragma unroll
            for (int r = 0; r < 4; r++) acc[i][j][r] = 0.f;

    const int nch = K / GBK;

    float4 pa0 = *(const float4*)(aptr);
    float4 pa1 = *(const float4*)(aptr + aoff2);
    float4 pb0 = *(const float4*)(bptr);
    float4 pb1 = *(const float4*)(bptr + boff2);

    {
        uint32_t t[4];
        t[0]=f2tf32(pa0.x); t[1]=f2tf32(pa0.y); t[2]=f2tf32(pa0.z); t[3]=f2tf32(pa0.w);
        *(uint4*)&As[0][ar][ac4 * 4] = *(uint4*)t;
        t[0]=f2tf32(pa1.x); t[1]=f2tf32(pa1.y); t[2]=f2tf32(pa1.z); t[3]=f2tf32(pa1.w);
        *(uint4*)&As[0][ar + 64][ac4 * 4] = *(uint4*)t;
        t[0]=f2tf32(pb0.x); t[1]=f2tf32(pb0.y); t[2]=f2tf32(pb0.z); t[3]=f2tf32(pb0.w);
        *(uint4*)&Bs[0][bk][bn4 * 4] = *(uint4*)t;
        t[0]=f2tf32(pb1.x); t[1]=f2tf32(pb1.y); t[2]=f2tf32(pb1.z); t[3]=f2tf32(pb1.w);
        *(uint4*)&Bs[0][bk + 8][bn4 * 4] = *(uint4*)t;
    }
    __syncthreads();

    for (int ch = 0; ch < nch; ch++) {
        const int buf = ch & 1;
        const int nxt = ch + 1;

        if (nxt < nch) {
            const float* ap = aptr + (size_t)nxt * GBK;
            const float* bp = bptr + (size_t)nxt * GBK * N;
            pa0 = *(const float4*)(ap);
            pa1 = *(const float4*)(ap + aoff2);
            pb0 = *(const float4*)(bp);
            pb1 = *(const float4*)(bp + boff2);
        }

        #pragma unroll
        for (int kk = 0; kk < 2; kk++) {
            const int kb = kk * 8;
            uint32_t af[4][4], bf[4][2];
            #pragma unroll
            for (int mi = 0; mi < 4; mi++) {
                const int r = warp_m + mi * 16 + gid;
                af[mi][0] = __float_as_uint(As[buf][r    ][kb + tid4]);
                af[mi][1] = __float_as_uint(As[buf][r + 8][kb + tid4]);
                af[mi][2] = __float_as_uint(As[buf][r    ][kb + tid4 + 4]);
                af[mi][3] = __float_as_uint(As[buf][r + 8][kb + tid4 + 4]);
            }
            #pragma unroll
            for (int ni = 0; ni < 4; ni++) {
                const int c = warp_n + ni * 8 + gid;
                bf[ni][0] = __float_as_uint(Bs[buf][kb + tid4    ][c]);
                bf[ni][1] = __float_as_uint(Bs[buf][kb + tid4 + 4][c]);
            }
            #pragma unroll
            for (int mi = 0; mi < 4; mi++)
                #pragma unroll
                for (int ni = 0; ni < 4; ni++)
                    mma_tf32(acc[mi][ni], af[mi][0], af[mi][1], af[mi][2], af[mi][3],
                             bf[ni][0], bf[ni][1]);
        }

        if (nxt < nch) {
            const int nb = nxt & 1;
            uint32_t t[4];
            t[0]=f2tf32(pa0.x); t[1]=f2tf32(pa0.y); t[2]=f2tf32(pa0.z); t[3]=f2tf32(pa0.w);
            *(uint4*)&As[nb][ar][ac4 * 4] = *(uint4*)t;
            t[0]=f2tf32(pa1.x); t[1]=f2tf32(pa1.y); t[2]=f2tf32(pa1.z); t[3]=f2tf32(pa1.w);
            *(uint4*)&As[nb][ar + 64][ac4 * 4] = *(uint4*)t;
            t[0]=f2tf32(pb0.x); t[1]=f2tf32(pb0.y); t[2]=f2tf32(pb0.z); t[3]=f2tf32(pb0.w);
            *(uint4*)&Bs[nb][bk][bn4 * 4] = *(uint4*)t;
            t[0]=f2tf32(pb1.x); t[1]=f2tf32(pb1.y); t[2]=f2tf32(pb1.z); t[3]=f2tf32(pb1.w);
            *(uint4*)&Bs[nb][bk + 8][bn4 * 4] = *(uint4*)t;
        }
        __syncthreads();
    }

    #pragma unroll
    for (int mi = 0; mi < 4; mi++) {
        const int r = m0 + warp_m + mi * 16 + gid;
        #pragma unroll
        for (int ni = 0; ni < 4; ni++) {
            const int c = n0 + warp_n + ni * 8 + tid4 * 2;
            *(float2*)(C + (size_t)r * N + c) =
                make_float2(acc[mi][ni][0], acc[mi][ni][1]);
            *(float2*)(C + (size_t)(r + 8) * N + c) =
                make_float2(acc[mi][ni][2], acc[mi][ni][3]);
        }
    }
}

// ---------------------------------------------------------------------------
// Fused RMSNorm + RoPE (unchanged)
// ---------------------------------------------------------------------------
__global__ void rmsnorm_rope(float* __restrict__ u, const float* __restrict__ w,
                             const float* __restrict__ fc, const float* __restrict__ fs,
                             int heads)
{
    const int token = blockIdx.x;
    const int t = token & (TT - 1);
    const int head = threadIdx.y;
    const int lane = threadIdx.x;

    float* base = u + ((size_t)token * heads + head) * HD;
    float4 v = *(float4*)(base + lane * 4);

    float ss = v.x * v.x + v.y * v.y + v.z * v.z + v.w * v.w;
    #pragma unroll
    for (int o = 16; o > 0; o >>= 1) ss += __shfl_xor_sync(0xFFFFFFFFu, ss, o);
    const float r = rsqrtf(ss * (1.f / HD) + 1e-6f);

    const float4 wv = *(const float4*)(w + lane * 4);
    const int p = lane * 2;
    const float c0 = fc[t * (HD / 2) + p],     s0 = fs[t * (HD / 2) + p];
    const float c1 = fc[t * (HD / 2) + p + 1], s1 = fs[t * (HD / 2) + p + 1];

    const float e0 = v.x * r * wv.x, o0 = v.y * r * wv.y;
    const float e1 = v.z * r * wv.z, o1 = v.w * r * wv.w;

    float4 out;
    out.x = e0 * c0 - o0 * s0;
    out.y = e0 * s0 + o0 * c0;
    out.z = e1 * c1 - o1 * s1;
    out.w = e1 * s1 + o1 * c1;
    *(float4*)(base + lane * 4) = out;
}

// ===========================================================================
// Tensor-core causal flash attention v2.
// TQ=128 (8 warps x m16), TK=64. Q fragments in registers (staged via smem).
// smem: Ks[64][132] + Vs[64][136] + Ps[128][68]  = 103.4 KB.
// Ks stride 132 -> QK^T B-frag banks 4*gid+tid4 (conflict-free).
// Vs stride 136 -> PV   B-frag banks 8*tid4+gid (conflict-free).
// LPT grid: qt = 15 - blockIdx.y (longest CTAs launch first).
// ===========================================================================
#define FTQ 128
#define FTK 64
#define KSTRK 132
#define KSTRV 136
#define PSTR 68
#define FA2_SMEM ((FTK * KSTRK + FTK * KSTRV + FTQ * PSTR) * (int)sizeof(float))

__device__ __forceinline__ float redmax4(float x) {
    x = fmaxf(x, __shfl_xor_sync(0xFFFFFFFFu, x, 1));
    x = fmaxf(x, __shfl_xor_sync(0xFFFFFFFFu, x, 2));
    return x;
}
__device__ __forceinline__ float redsum4(float x) {
    x += __shfl_xor_sync(0xFFFFFFFFu, x, 1);
    x += __shfl_xor_sync(0xFFFFFFFFu, x, 2);
    return x;
}

__global__ __launch_bounds__(256) void flash_tc(
    const float* __restrict__ q, const float* __restrict__ k,
    const float* __restrict__ v, float* __restrict__ o)
{
    extern __shared__ float sm[];
    float* Ks = sm;                       // [64][132]
    float* Vs = Ks + FTK * KSTRK;         // [64][136]
    float* Ps = Vs + FTK * KSTRV;         // [128][68]

    // LPT schedule: longest q-tiles first
    const int qt = (TT / FTQ - 1) - blockIdx.y;
    const int hb = blockIdx.x;            // b*HH + h
    const int h  = hb % HH;
    const int b  = hb / HH;
    const int g  = h / REP;
    const int tid  = threadIdx.x;
    const int wid  = tid >> 5;
    const int lane = tid & 31;
    const int gid  = lane >> 2;
    const int tid4 = lane & 3;
    const int q0 = qt * FTQ;
    const int wq = wid * 16;              // warp q-row base within tile

    // --- Stage this warp's 16 Q rows into warp-private smem, coalesced ---
    // warps 0-3 use Ks rows wid*16..; warps 4-7 use Vs rows (wid-4)*16..
    const int sstr = (wid < 4) ? KSTRK : KSTRV;
    float* Sg = (wid < 4) ? (Ks + wq * KSTRK) : (Vs + (wq - 64) * KSTRV);
    #pragma unroll
    for (int it = 0; it < 16; it++) {
        const int i = lane + it * 32;
        const int r = i >> 5, c4 = i & 31;
        const float4 qv = *(const float4*)(
            q + ((size_t)(b * TT + q0 + wq + r) * HH + h) * HD + c4 * 4);
        uint32_t t[4] = {f2tf32(qv.x), f2tf32(qv.y), f2tf32(qv.z), f2tf32(qv.w)};
        *(uint4*)&Sg[r * sstr + c4 * 4] = *(uint4*)t;
    }
    __syncwarp();

    // --- Pull Q fragments into registers (16 kfrags x 4 regs) ---
    uint32_t qf[16][4];
    #pragma unroll
    for (int kf = 0; kf < 16; kf++) {
        const int kb = kf * 8;
        qf[kf][0] = __float_as_uint(Sg[gid * sstr + kb + tid4]);
        qf[kf][1] = __float_as_uint(Sg[(gid + 8) * sstr + kb + tid4]);
        qf[kf][2] = __float_as_uint(Sg[gid * sstr + kb + tid4 + 4]);
        qf[kf][3] = __float_as_uint(Sg[(gid + 8) * sstr + kb + tid4 + 4]);
    }

    float oacc[16][4];
    #pragma unroll
    for (int i = 0; i < 16; i++)
        #pragma unroll
        for (int j = 0; j < 4; j++) oacc[i][j] = 0.f;
    float m0r = -1e30f, m1r = -1e30f, l0r = 0.f, l1r = 0.f;

    const float scale = 0.08838834764831845f;  // 1/sqrt(128)
    const int r0 = q0 + wq + gid;
    const int r1 = r0 + 8;
    const int nkt = 2 * qt + 2;

    for (int kt = 0; kt < nkt; kt++) {
        const int k0 = kt * FTK;
        __syncthreads();  // staging / prev-iter consumers done with Ks/Vs

        // Load K,V tiles (fp32 -> tf32)
        #pragma unroll 2
        for (int i = tid; i < FTK * 32; i += 256) {
            const int r = i >> 5, c4 = i & 31;
            const size_t gbase = ((size_t)(b * TT + k0 + r) * KVH + g) * HD + c4 * 4;
            const float4 kv = *(const float4*)(k + gbase);
            const float4 vv = *(const float4*)(v + gbase);
            uint32_t t[4] = {f2tf32(kv.x), f2tf32(kv.y), f2tf32(kv.z), f2tf32(kv.w)};
            *(uint4*)&Ks[r * KSTRK + c4 * 4] = *(uint4*)t;
            uint32_t u[4] = {f2tf32(vv.x), f2tf32(vv.y), f2tf32(vv.z), f2tf32(vv.w)};
            *(uint4*)&Vs[r * KSTRV + c4 * 4] = *(uint4*)u;
        }
        __syncthreads();

        // --- S = Q K^T : 8 n-tiles x 16 k-frags, Q from registers ---
        float sacc[8][4];
        #pragma unroll
        for (int nt = 0; nt < 8; nt++)
            #pragma unroll
            for (int j = 0; j < 4; j++) sacc[nt][j] = 0.f;

        #pragma unroll
        for (int kf = 0; kf < 16; kf++) {
            const int kb = kf * 8;
            #pragma unroll
            for (int nt = 0; nt < 8; nt++) {
                const uint32_t b0 = __float_as_uint(Ks[(nt * 8 + gid) * KSTRK + kb + tid4]);
                const uint32_t b1 = __float_as_uint(Ks[(nt * 8 + gid) * KSTRK + kb + tid4 + 4]);
                mma_tf32(sacc[nt], qf[kf][0], qf[kf][1], qf[kf][2], qf[kf][3], b0, b1);
            }
        }

        // --- scale + (conditional) causal mask + row max ---
        float mn0 = m0r, mn1 = m1r;
        if (k0 + FTK - 1 > q0 + wq) {   // warp-uniform: tile touches diagonal
            #pragma unroll
            for (int nt = 0; nt < 8; nt++) {
                const int c = k0 + nt * 8 + tid4 * 2;
                float s0 = sacc[nt][0] * scale, s1 = sacc[nt][1] * scale;
                float s2 = sacc[nt][2] * scale, s3 = sacc[nt][3] * scale;
                if (c     > r0) s0 = -1e30f;
                if (c + 1 > r0) s1 = -1e30f;
                if (c     > r1) s2 = -1e30f;
                if (c + 1 > r1) s3 = -1e30f;
                sacc[nt][0] = s0; sacc[nt][1] = s1; sacc[nt][2] = s2; sacc[nt][3] = s3;
                mn0 = fmaxf(mn0, fmaxf(s0, s1));
                mn1 = fmaxf(mn1, fmaxf(s2, s3));
            }
        } else {
            #pragma unroll
            for (int nt = 0; nt < 8; nt++) {
                const float s0 = sacc[nt][0] * scale, s1 = sacc[nt][1] * scale;
                const float s2 = sacc[nt][2] * scale, s3 = sacc[nt][3] * scale;
                sacc[nt][0] = s0; sacc[nt][1] = s1; sacc[nt][2] = s2; sacc[nt][3] = s3;
                mn0 = fmaxf(mn0, fmaxf(s0, s1));
                mn1 = fmaxf(mn1, fmaxf(s2, s3));
            }
        }
        mn0 = redmax4(mn0);
        mn1 = redmax4(mn1);

        // --- online softmax: rescale, exp, write P (tf32) ---
        const float corr0 = __expf(m0r - mn0);
        const float corr1 = __expf(m1r - mn1);
        float ps0 = 0.f, ps1 = 0.f;
        #pragma unroll
        for (int nt = 0; nt < 8; nt++) {
            const float p0 = __expf(sacc[nt][0] - mn0);
            const float p1 = __expf(sacc[nt][1] - mn0);
            const float p2 = __expf(sacc[nt][2] - mn1);
            const float p3 = __expf(sacc[nt][3] - mn1);
            ps0 += p0 + p1;
            ps1 += p2 + p3;
            const int cc = nt * 8 + 2 * tid4;
            *(float2*)&Ps[(wq + gid) * PSTR + cc] =
                make_float2(__uint_as_float(f2tf32(p0)), __uint_as_float(f2tf32(p1)));
            *(float2*)&Ps[(wq + gid + 8) * PSTR + cc] =
                make_float2(__uint_as_float(f2tf32(p2)), __uint_as_float(f2tf32(p3)));
        }
        l0r = l0r * corr0 + redsum4(ps0);
        l1r = l1r * corr1 + redsum4(ps1);
        m0r = mn0; m1r = mn1;

        #pragma unroll
        for (int nt = 0; nt < 16; nt++) {
            oacc[nt][0] *= corr0; oacc[nt][1] *= corr0;
            oacc[nt][2] *= corr1; oacc[nt][3] *= corr1;
        }
        __syncwarp();  // P rows are warp-private

        // --- O += P V : 16 n-tiles x 8 k-frags ---
        #pragma unroll
        for (int kf = 0; kf < 8; kf++) {
            const int kb = kf * 8;
            const uint32_t a0 = __float_as_uint(Ps[(wq + gid) * PSTR + kb + tid4]);
            const uint32_t a1 = __float_as_uint(Ps[(wq + gid + 8) * PSTR + kb + tid4]);
            const uint32_t a2 = __float_as_uint(Ps[(wq + gid) * PSTR + kb + tid4 + 4]);
            const uint32_t a3 = __float_as_uint(Ps[(wq + gid + 8) * PSTR + kb + tid4 + 4]);
            #pragma unroll
            for (int nt = 0; nt < 16; nt++) {
                const uint32_t b0 = __float_as_uint(Vs[(kb + tid4) * KSTRV + nt * 8 + gid]);
                const uint32_t b1 = __float_as_uint(Vs[(kb + tid4 + 4) * KSTRV + nt * 8 + gid]);
                mma_tf32(oacc[nt], a0, a1, a2, a3, b0, b1);
            }
        }
    }

    // Epilogue: normalize and store
    const float rl0 = 1.f / l0r;
    const float rl1 = 1.f / l1r;
    float* ob0 = o + ((size_t)(b * TT + r0) * HH + h) * HD;
    float* ob1 = o + ((size_t)(b * TT + r1) * HH + h) * HD;
    #pragma unroll
    for (int nt = 0; nt < 16; nt++) {
        const int c = nt * 8 + 2 * tid4;
        *(float2*)(ob0 + c) = make_float2(oacc[nt][0] * rl0, oacc[nt][1] * rl0);
        *(float2*)(ob1 + c) = make_float2(oacc[nt][2] * rl1, oacc[nt][3] * rl1);
    }
}

// ---------------------------------------------------------------------------
extern "C" void kernel_launch(void* const* d_in, const int* in_sizes, int n_in,
                              void* d_out, int out_size)
{
    const float* x    = (const float*)d_in[0];
    const float* wq   = (const float*)d_in[1];
    const float* wk   = (const float*)d_in[2];
    const float* wv   = (const float*)d_in[3];
    const float* wo   = (const float*)d_in[4];
    const float* qnw  = (const float*)d_in[5];
    const float* knw  = (const float*)d_in[6];
    const float* fcos = (const float*)d_in[7];
    const float* fsin = (const float*)d_in[8];
    float* out = (float*)d_out;

    float *q, *k, *v, *att;
    cudaGetSymbolAddress((void**)&q,   g_q);
    cudaGetSymbolAddress((void**)&k,   g_k);
    cudaGetSymbolAddress((void**)&v,   g_v);
    cudaGetSymbolAddress((void**)&att, g_att);

    cudaFuncSetAttribute(flash_tc, cudaFuncAttributeMaxDynamicSharedMemorySize, FA2_SMEM);

    // Projections (tensor core tf32 via mma.sync)
    gemm_mma<<<dim3((HH * HD) / GBN, NTOK / GBM), 256>>>(NTOK, HH * HD, DD, x, wq, q);
    gemm_mma<<<dim3((KVH * HD) / GBN, NTOK / GBM), 256>>>(NTOK, KVH * HD, DD, x, wk, k);
    gemm_mma<<<dim3((KVH * HD) / GBN, NTOK / GBM), 256>>>(NTOK, KVH * HD, DD, x, wv, v);

    // RMSNorm + RoPE (in place)
    rmsnorm_rope<<<NTOK, dim3(32, HH)>>>(q, qnw, fcos, fsin, HH);
    rmsnorm_rope<<<NTOK, dim3(32, KVH)>>>(k, knw, fcos, fsin, KVH);

    // Tensor-core flash attention (LPT order: longest q-tiles first)
    flash_tc<<<dim3(HH * BB, TT / FTQ), 256, FA2_SMEM>>>(q, k, v, att);

    // Output projection
    gemm_mma<<<dim3(DD / GBN, NTOK / GBM), 256>>>(NTOK, DD, HH * HD, att, wo, out);
}

// round 8
// speedup vs baseline: 9.4467x; 1.0405x over previous
#include <cuda_runtime.h>
#include <cuda_bf16.h>
#include <math.h>
#include <cstdint>

// Problem constants
#define BB 2
#define TT 2048
#define DD 2048
#define HH 16
#define KVH 4
#define HD 128
#define REP (HH / KVH)
#define NTOK (BB * TT)   // 4096

// Scratch (device globals — no allocation allowed)
__device__ float g_q[(size_t)NTOK * HH * HD];    // 32 MB
__device__ float g_k[(size_t)NTOK * KVH * HD];   // 8 MB
__device__ float g_v[(size_t)NTOK * KVH * HD];   // 8 MB
__device__ float g_att[(size_t)NTOK * HH * HD];  // 32 MB

__device__ __forceinline__ uint32_t f2tf32(float f) {
    uint32_t r;
    asm("cvt.rna.tf32.f32 %0, %1;" : "=r"(r) : "f"(f));
    return r;
}

__device__ __forceinline__ uint32_t smem_u32(const void* p) {
    uint32_t a;
    asm("{ .reg .u64 t; cvta.to.shared.u64 t, %1; cvt.u32.u64 %0, t; }"
        : "=r"(a) : "l"(p));
    return a;
}

__device__ __forceinline__ void mma_tf32(float c[4],
    uint32_t a0, uint32_t a1, uint32_t a2, uint32_t a3,
    uint32_t b0, uint32_t b1)
{
    asm volatile(
        "mma.sync.aligned.m16n8k8.row.col.f32.tf32.tf32.f32 "
        "{%0,%1,%2,%3}, {%4,%5,%6,%7}, {%8,%9}, {%0,%1,%2,%3};"
        : "+f"(c[0]), "+f"(c[1]), "+f"(c[2]), "+f"(c[3])
        : "r"(a0), "r"(a1), "r"(a2), "r"(a3), "r"(b0), "r"(b1));
}

__device__ __forceinline__ void cpa16(uint32_t dst, const float* src) {
    asm volatile("cp.async.cg.shared.global [%0], [%1], 16;"
                 :: "r"(dst), "l"(src));
}
#define CP_COMMIT() asm volatile("cp.async.commit_group;" ::: "memory")
#define CP_WAIT(n)  asm volatile("cp.async.wait_group %0;" :: "n"(n) : "memory")

// ===========================================================================
// tf32 mma.sync GEMM (unchanged — passing)
// ===========================================================================
#define GBM 128
#define GBN 128
#define GBK 16
#define ASTR (GBK + 4)
#define BSTR (GBN + 8)

__global__ __launch_bounds__(256) void gemm_mma(
    int M, int N, int K,
    const float* __restrict__ A, const float* __restrict__ B,
    float* __restrict__ C)
{
    __shared__ float As[2][GBM][ASTR];
    __shared__ float Bs[2][GBK][BSTR];

    const int tid  = threadIdx.x;
    const int wid  = tid >> 5;
    const int lane = tid & 31;
    const int gid  = lane >> 2;
    const int tid4 = lane & 3;

    const int warp_m = (wid & 1) * 64;
    const int warp_n = (wid >> 1) * 32;

    const int m0 = blockIdx.y * GBM;
    const int n0 = blockIdx.x * GBN;

    const int ar  = tid >> 2;
    const int ac4 = tid & 3;
    const int bk  = tid >> 5;
    const int bn4 = tid & 31;

    const float* aptr = A + (size_t)(m0 + ar) * K + ac4 * 4;
    const float* bptr = B + (size_t)bk * N + n0 + bn4 * 4;
    const size_t aoff2 = (size_t)64 * K;
    const size_t boff2 = (size_t)8 * N;

    float acc[4][4][4];
    #pragma unroll
    for (int i = 0; i < 4; i++)
        #pragma unroll
        for (int j = 0; j < 4; j++)
            #pragma unroll
            for (int r = 0; r < 4; r++) acc[i][j][r] = 0.f;

    const int nch = K / GBK;

    float4 pa0 = *(const float4*)(aptr);
    float4 pa1 = *(const float4*)(aptr + aoff2);
    float4 pb0 = *(const float4*)(bptr);
    float4 pb1 = *(const float4*)(bptr + boff2);

    {
        uint32_t t[4];
        t[0]=f2tf32(pa0.x); t[1]=f2tf32(pa0.y); t[2]=f2tf32(pa0.z); t[3]=f2tf32(pa0.w);
        *(uint4*)&As[0][ar][ac4 * 4] = *(uint4*)t;
        t[0]=f2tf32(pa1.x); t[1]=f2tf32(pa1.y); t[2]=f2tf32(pa1.z); t[3]=f2tf32(pa1.w);
        *(uint4*)&As[0][ar + 64][ac4 * 4] = *(uint4*)t;
        t[0]=f2tf32(pb0.x); t[1]=f2tf32(pb0.y); t[2]=f2tf32(pb0.z); t[3]=f2tf32(pb0.w);
        *(uint4*)&Bs[0][bk][bn4 * 4] = *(uint4*)t;
        t[0]=f2tf32(pb1.x); t[1]=f2tf32(pb1.y); t[2]=f2tf32(pb1.z); t[3]=f2tf32(pb1.w);
        *(uint4*)&Bs[0][bk + 8][bn4 * 4] = *(uint4*)t;
    }
    __syncthreads();

    for (int ch = 0; ch < nch; ch++) {
        const int buf = ch & 1;
        const int nxt = ch + 1;

        if (nxt < nch) {
            const float* ap = aptr + (size_t)nxt * GBK;
            const float* bp = bptr + (size_t)nxt * GBK * N;
            pa0 = *(const float4*)(ap);
            pa1 = *(const float4*)(ap + aoff2);
            pb0 = *(const float4*)(bp);
            pb1 = *(const float4*)(bp + boff2);
        }

        #pragma unroll
        for (int kk = 0; kk < 2; kk++) {
            const int kb = kk * 8;
            uint32_t af[4][4], bf[4][2];
            #pragma unroll
            for (int mi = 0; mi < 4; mi++) {
                const int r = warp_m + mi * 16 + gid;
                af[mi][0] = __float_as_uint(As[buf][r    ][kb + tid4]);
                af[mi][1] = __float_as_uint(As[buf][r + 8][kb + tid4]);
                af[mi][2] = __float_as_uint(As[buf][r    ][kb + tid4 + 4]);
                af[mi][3] = __float_as_uint(As[buf][r + 8][kb + tid4 + 4]);
            }
            #pragma unroll
            for (int ni = 0; ni < 4; ni++) {
                const int c = warp_n + ni * 8 + gid;
                bf[ni][0] = __float_as_uint(Bs[buf][kb + tid4    ][c]);
                bf[ni][1] = __float_as_uint(Bs[buf][kb + tid4 + 4][c]);
            }
            #pragma unroll
            for (int mi = 0; mi < 4; mi++)
                #pragma unroll
                for (int ni = 0; ni < 4; ni++)
                    mma_tf32(acc[mi][ni], af[mi][0], af[mi][1], af[mi][2], af[mi][3],
                             bf[ni][0], bf[ni][1]);
        }

        if (nxt < nch) {
            const int nb = nxt & 1;
            uint32_t t[4];
            t[0]=f2tf32(pa0.x); t[1]=f2tf32(pa0.y); t[2]=f2tf32(pa0.z); t[3]=f2tf32(pa0.w);
            *(uint4*)&As[nb][ar][ac4 * 4] = *(uint4*)t;
            t[0]=f2tf32(pa1.x); t[1]=f2tf32(pa1.y); t[2]=f2tf32(pa1.z); t[3]=f2tf32(pa1.w);
            *(uint4*)&As[nb][ar + 64][ac4 * 4] = *(uint4*)t;
            t[0]=f2tf32(pb0.x); t[1]=f2tf32(pb0.y); t[2]=f2tf32(pb0.z); t[3]=f2tf32(pb0.w);
            *(uint4*)&Bs[nb][bk][bn4 * 4] = *(uint4*)t;
            t[0]=f2tf32(pb1.x); t[1]=f2tf32(pb1.y); t[2]=f2tf32(pb1.z); t[3]=f2tf32(pb1.w);
            *(uint4*)&Bs[nb][bk + 8][bn4 * 4] = *(uint4*)t;
        }
        __syncthreads();
    }

    #pragma unroll
    for (int mi = 0; mi < 4; mi++) {
        const int r = m0 + warp_m + mi * 16 + gid;
        #pragma unroll
        for (int ni = 0; ni < 4; ni++) {
            const int c = n0 + warp_n + ni * 8 + tid4 * 2;
            *(float2*)(C + (size_t)r * N + c) =
                make_float2(acc[mi][ni][0], acc[mi][ni][1]);
            *(float2*)(C + (size_t)(r + 8) * N + c) =
                make_float2(acc[mi][ni][2], acc[mi][ni][3]);
        }
    }
}

// ---------------------------------------------------------------------------
// Fused RMSNorm + RoPE (unchanged)
// ---------------------------------------------------------------------------
__global__ void rmsnorm_rope(float* __restrict__ u, const float* __restrict__ w,
                             const float* __restrict__ fc, const float* __restrict__ fs,
                             int heads)
{
    const int token = blockIdx.x;
    const int t = token & (TT - 1);
    const int head = threadIdx.y;
    const int lane = threadIdx.x;

    float* base = u + ((size_t)token * heads + head) * HD;
    float4 v = *(float4*)(base + lane * 4);

    float ss = v.x * v.x + v.y * v.y + v.z * v.z + v.w * v.w;
    #pragma unroll
    for (int o = 16; o > 0; o >>= 1) ss += __shfl_xor_sync(0xFFFFFFFFu, ss, o);
    const float r = rsqrtf(ss * (1.f / HD) + 1e-6f);

    const float4 wv = *(const float4*)(w + lane * 4);
    const int p = lane * 2;
    const float c0 = fc[t * (HD / 2) + p],     s0 = fs[t * (HD / 2) + p];
    const float c1 = fc[t * (HD / 2) + p + 1], s1 = fs[t * (HD / 2) + p + 1];

    const float e0 = v.x * r * wv.x, o0 = v.y * r * wv.y;
    const float e1 = v.z * r * wv.z, o1 = v.w * r * wv.w;

    float4 out;
    out.x = e0 * c0 - o0 * s0;
    out.y = e0 * s0 + o0 * c0;
    out.z = e1 * c1 - o1 * s1;
    out.w = e1 * s1 + o1 * c1;
    *(float4*)(base + lane * 4) = out;
}

// ===========================================================================
// Tensor-core causal flash attention v3 — software pipelined.
// TQ=128 (8 warps x m16), TK=64. cp.async double-buffered K/V (raw fp32 fed
// to tf32 mma = HW truncation; Q and P still cvt.rna). Per iteration:
// PV(kt) + S(kt+1) back-to-back mma, then one softmax. 2 barriers/iter.
// smem: 2*Ks[64][132] + 2*Vs[64][136] + Ps[128][68] = 172032 B. 1 CTA/SM.
// ===========================================================================
#define FTQ 128
#define FTK 64
#define KSTRK 132
#define KSTRV 136
#define PSTR 68
#define FA3_SMEM ((2 * FTK * KSTRK + 2 * FTK * KSTRV + FTQ * PSTR) * (int)sizeof(float))

__device__ __forceinline__ float redmax4(float x) {
    x = fmaxf(x, __shfl_xor_sync(0xFFFFFFFFu, x, 1));
    x = fmaxf(x, __shfl_xor_sync(0xFFFFFFFFu, x, 2));
    return x;
}
__device__ __forceinline__ float redsum4(float x) {
    x += __shfl_xor_sync(0xFFFFFFFFu, x, 1);
    x += __shfl_xor_sync(0xFFFFFFFFu, x, 2);
    return x;
}

__device__ __forceinline__ void issue_kv_tile(
    const float* __restrict__ src, int b, int g, int kt, uint32_t smem_base,
    int stride, int tid)
{
    const int t0 = b * TT + kt * FTK;
    #pragma unroll
    for (int it = 0; it < 8; it++) {
        const int i = tid + it * 256;
        const int r = i >> 5, c4 = i & 31;
        const float* s = src + ((size_t)(t0 + r) * KVH + g) * HD + c4 * 4;
        cpa16(smem_base + (uint32_t)(r * stride + c4 * 4) * 4u, s);
    }
}

__global__ __launch_bounds__(256) void flash_tc(
    const float* __restrict__ q, const float* __restrict__ k,
    const float* __restrict__ v, float* __restrict__ o)
{
    extern __shared__ float sm[];
    float* Ks0 = sm;
    float* Ks1 = Ks0 + FTK * KSTRK;
    float* Vs0 = Ks1 + FTK * KSTRK;
    float* Vs1 = Vs0 + FTK * KSTRV;
    float* Ps  = Vs1 + FTK * KSTRV;
    const uint32_t ks0u = smem_u32(Ks0);
    const uint32_t ks1u = smem_u32(Ks1);
    const uint32_t vs0u = smem_u32(Vs0);
    const uint32_t vs1u = smem_u32(Vs1);

    // LPT schedule: longest q-tiles first
    const int qt = (TT / FTQ - 1) - blockIdx.y;
    const int hb = blockIdx.x;            // b*HH + h
    const int h  = hb % HH;
    const int b  = hb / HH;
    const int g  = h / REP;
    const int tid  = threadIdx.x;
    const int wid  = tid >> 5;
    const int lane = tid & 31;
    const int gid  = lane >> 2;
    const int tid4 = lane & 3;
    const int q0 = qt * FTQ;
    const int wq = wid * 16;

    // --- Stage Q (cvt.rna) into Ks1/Vs1 scratch, pull fragments to regs ---
    const int sstr = (wid < 4) ? KSTRK : KSTRV;
    float* Sg = (wid < 4) ? (Ks1 + wq * KSTRK) : (Vs1 + (wq - 64) * KSTRV);
    #pragma unroll
    for (int it = 0; it < 16; it++) {
        const int i = lane + it * 32;
        const int r = i >> 5, c4 = i & 31;
        const float4 qv = *(const float4*)(
            q + ((size_t)(b * TT + q0 + wq + r) * HH + h) * HD + c4 * 4);
        uint32_t t[4] = {f2tf32(qv.x), f2tf32(qv.y), f2tf32(qv.z), f2tf32(qv.w)};
        *(uint4*)&Sg[r * sstr + c4 * 4] = *(uint4*)t;
    }
    __syncwarp();
    uint32_t qf[16][4];
    #pragma unroll
    for (int kf = 0; kf < 16; kf++) {
        const int kb = kf * 8;
        qf[kf][0] = __float_as_uint(Sg[gid * sstr + kb + tid4]);
        qf[kf][1] = __float_as_uint(Sg[(gid + 8) * sstr + kb + tid4]);
        qf[kf][2] = __float_as_uint(Sg[gid * sstr + kb + tid4 + 4]);
        qf[kf][3] = __float_as_uint(Sg[(gid + 8) * sstr + kb + tid4 + 4]);
    }
    __syncthreads();   // all staging reads done before cp.async may land

    const int nkt = 2 * qt + 2;

    // Preload tile 0 (K then V as separate groups)
    issue_kv_tile(k, b, g, 0, ks0u, KSTRK, tid); CP_COMMIT();
    issue_kv_tile(v, b, g, 0, vs0u, KSTRV, tid); CP_COMMIT();

    float oacc[16][4];
    #pragma unroll
    for (int i = 0; i < 16; i++)
        #pragma unroll
        for (int j = 0; j < 4; j++) oacc[i][j] = 0.f;
    float m0r = -1e30f, m1r = -1e30f, l0r = 0.f, l1r = 0.f;

    const float scale = 0.08838834764831845f;  // 1/sqrt(128)
    const int r0 = q0 + wq + gid;
    const int r1 = r0 + 8;

    for (int kt = -1; kt < nkt; kt++) {
        const int cb = kt & 1;   // (-1)&1 == 1

        // s1: prefetch K(kt+2) into Ks[cb] (its last reader, S(kt), finished
        //     before the s4 barrier of the previous iteration)
        if (kt + 2 < nkt) {
            issue_kv_tile(k, b, g, kt + 2, cb ? ks1u : ks0u, KSTRK, tid);
            CP_COMMIT();
        }
        // s2: wait until V(kt) and K(kt+1) have landed, then make visible
        if (kt + 2 < nkt)      { CP_WAIT(2); }
        else if (kt + 1 < nkt) { CP_WAIT(1); }
        else                   { CP_WAIT(0); }
        __syncthreads();

        // s3a: O += P(kt) V(kt)
        if (kt >= 0) {
            const float* Vb = cb ? Vs1 : Vs0;
            #pragma unroll
            for (int kf = 0; kf < 8; kf++) {
                const int kb = kf * 8;
                const uint32_t a0 = __float_as_uint(Ps[(wq + gid) * PSTR + kb + tid4]);
                const uint32_t a1 = __float_as_uint(Ps[(wq + gid + 8) * PSTR + kb + tid4]);
                const uint32_t a2 = __float_as_uint(Ps[(wq + gid) * PSTR + kb + tid4 + 4]);
                const uint32_t a3 = __float_as_uint(Ps[(wq + gid + 8) * PSTR + kb + tid4 + 4]);
                #pragma unroll
                for (int nt = 0; nt < 16; nt++) {
                    const uint32_t b0 = __float_as_uint(Vb[(kb + tid4) * KSTRV + nt * 8 + gid]);
                    const uint32_t b1 = __float_as_uint(Vb[(kb + tid4 + 4) * KSTRV + nt * 8 + gid]);
                    mma_tf32(oacc[nt], a0, a1, a2, a3, b0, b1);
                }
            }
        }
        // s3b: S(kt+1) = Q K(kt+1)^T
        float sacc[8][4];
        if (kt + 1 < nkt) {
            const float* Kb = cb ? Ks0 : Ks1;   // parity (kt+1)&1
            #pragma unroll
            for (int nt = 0; nt < 8; nt++)
                #pragma unroll
                for (int j = 0; j < 4; j++) sacc[nt][j] = 0.f;
            #pragma unroll
            for (int kf = 0; kf < 16; kf++) {
                const int kb = kf * 8;
                #pragma unroll
                for (int nt = 0; nt < 8; nt++) {
                    const uint32_t b0 = __float_as_uint(Kb[(nt * 8 + gid) * KSTRK + kb + tid4]);
                    const uint32_t b1 = __float_as_uint(Kb[(nt * 8 + gid) * KSTRK + kb + tid4 + 4]);
                    mma_tf32(sacc[nt], qf[kf][0], qf[kf][1], qf[kf][2], qf[kf][3], b0, b1);
                }
            }
        }

        // s4: all PV(kt) reads done -> prefetch V(kt+2) into Vs[cb]
        __syncthreads();
        if (kt + 2 < nkt) {
            issue_kv_tile(v, b, g, kt + 2, cb ? vs1u : vs0u, KSTRV, tid);
            CP_COMMIT();
        }

        // s5: softmax(kt+1)
        if (kt + 1 < nkt) {
            const int k0 = (kt + 1) * FTK;
            float mn0 = m0r, mn1 = m1r;
            if (k0 + FTK - 1 > q0 + wq) {   // warp-uniform diagonal check
                #pragma unroll
                for (int nt = 0; nt < 8; nt++) {
                    const int c = k0 + nt * 8 + tid4 * 2;
                    float s0 = sacc[nt][0] * scale, s1 = sacc[nt][1] * scale;
                    float s2 = sacc[nt][2] * scale, s3 = sacc[nt][3] * scale;
                    if (c     > r0) s0 = -1e30f;
                    if (c + 1 > r0) s1 = -1e30f;
                    if (c     > r1) s2 = -1e30f;
                    if (c + 1 > r1) s3 = -1e30f;
                    sacc[nt][0] = s0; sacc[nt][1] = s1; sacc[nt][2] = s2; sacc[nt][3] = s3;
                    mn0 = fmaxf(mn0, fmaxf(s0, s1));
                    mn1 = fmaxf(mn1, fmaxf(s2, s3));
                }
            } else {
                #pragma unroll
                for (int nt = 0; nt < 8; nt++) {
                    const float s0 = sacc[nt][0] * scale, s1 = sacc[nt][1] * scale;
                    const float s2 = sacc[nt][2] * scale, s3 = sacc[nt][3] * scale;
                    sacc[nt][0] = s0; sacc[nt][1] = s1; sacc[nt][2] = s2; sacc[nt][3] = s3;
                    mn0 = fmaxf(mn0, fmaxf(s0, s1));
                    mn1 = fmaxf(mn1, fmaxf(s2, s3));
                }
            }
            mn0 = redmax4(mn0);
            mn1 = redmax4(mn1);

            const float corr0 = __expf(m0r - mn0);
            const float corr1 = __expf(m1r - mn1);
            float ps0 = 0.f, ps1 = 0.f;
            #pragma unroll
            for (int nt = 0; nt < 8; nt++) {
                const float p0 = __expf(sacc[nt][0] - mn0);
                const float p1 = __expf(sacc[nt][1] - mn0);
                const float p2 = __expf(sacc[nt][2] - mn1);
                const float p3 = __expf(sacc[nt][3] - mn1);
                ps0 += p0 + p1;
                ps1 += p2 + p3;
                const int cc = nt * 8 + 2 * tid4;
                *(float2*)&Ps[(wq + gid) * PSTR + cc] =
                    make_float2(__uint_as_float(f2tf32(p0)), __uint_as_float(f2tf32(p1)));
                *(float2*)&Ps[(wq + gid + 8) * PSTR + cc] =
                    make_float2(__uint_as_float(f2tf32(p2)), __uint_as_float(f2tf32(p3)));
            }
            l0r = l0r * corr0 + redsum4(ps0);
            l1r = l1r * corr1 + redsum4(ps1);
            m0r = mn0; m1r = mn1;

            #pragma unroll
            for (int nt = 0; nt < 16; nt++) {
                oacc[nt][0] *= corr0; oacc[nt][1] *= corr0;
                oacc[nt][2] *= corr1; oacc[nt][3] *= corr1;
            }
            __syncwarp();   // Ps rows warp-private: writes visible to lanes
        }
    }

    // Epilogue: normalize and store
    const float rl0 = 1.f / l0r;
    const float rl1 = 1.f / l1r;
    float* ob0 = o + ((size_t)(b * TT + r0) * HH + h) * HD;
    float* ob1 = o + ((size_t)(b * TT + r1) * HH + h) * HD;
    #pragma unroll
    for (int nt = 0; nt < 16; nt++) {
        const int c = nt * 8 + 2 * tid4;
        *(float2*)(ob0 + c) = make_float2(oacc[nt][0] * rl0, oacc[nt][1] * rl0);
        *(float2*)(ob1 + c) = make_float2(oacc[nt][2] * rl1, oacc[nt][3] * rl1);
    }
}

// ---------------------------------------------------------------------------
extern "C" void kernel_launch(void* const* d_in, const int* in_sizes, int n_in,
                              void* d_out, int out_size)
{
    const float* x    = (const float*)d_in[0];
    const float* wq   = (const float*)d_in[1];
    const float* wk   = (const float*)d_in[2];
    const float* wv   = (const float*)d_in[3];
    const float* wo   = (const float*)d_in[4];
    const float* qnw  = (const float*)d_in[5];
    const float* knw  = (const float*)d_in[6];
    const float* fcos = (const float*)d_in[7];
    const float* fsin = (const float*)d_in[8];
    float* out = (float*)d_out;

    float *q, *k, *v, *att;
    cudaGetSymbolAddress((void**)&q,   g_q);
    cudaGetSymbolAddress((void**)&k,   g_k);
    cudaGetSymbolAddress((void**)&v,   g_v);
    cudaGetSymbolAddress((void**)&att, g_att);

    cudaFuncSetAttribute(flash_tc, cudaFuncAttributeMaxDynamicSharedMemorySize, FA3_SMEM);

    // Projections (tensor core tf32 via mma.sync)
    gemm_mma<<<dim3((HH * HD) / GBN, NTOK / GBM), 256>>>(NTOK, HH * HD, DD, x, wq, q);
    gemm_mma<<<dim3((KVH * HD) / GBN, NTOK / GBM), 256>>>(NTOK, KVH * HD, DD, x, wk, k);
    gemm_mma<<<dim3((KVH * HD) / GBN, NTOK / GBM), 256>>>(NTOK, KVH * HD, DD, x, wv, v);

    // RMSNorm + RoPE (in place)
    rmsnorm_rope<<<NTOK, dim3(32, HH)>>>(q, qnw, fcos, fsin, HH);
    rmsnorm_rope<<<NTOK, dim3(32, KVH)>>>(k, knw, fcos, fsin, KVH);

    // Tensor-core flash attention (pipelined, LPT order)
    flash_tc<<<dim3(HH * BB, TT / FTQ), 256, FA3_SMEM>>>(q, k, v, att);

    // Output projection
    gemm_mma<<<dim3(DD / GBN, NTOK / GBM), 256>>>(NTOK, DD, HH * HD, att, wo, out);
}